// round 12
// baseline (speedup 1.0000x reference)
#include <cuda_runtime.h>
#include <stdint.h>

#define HW      49
#define MPAD    64        // p padded
#define CT      128       // c per CTA
#define CCOLS   512
#define THREADS 512
#define SA      36        // A row stride in uint2 (36 ≡ 4 mod 16 -> conflict-free frags)
#define SB      132       // B row stride in uint2 (132 ≡ 4 mod 16 -> conflict-free frags)
#define NKP     32        // kpairs (K padded 49 -> 64)

// smem: Apk[64][36] uint2 (18432 B) | Bpk[32][132] uint2 (33792 B); Y reuses B
#define SMEM_BYTES (MPAD*SA*8 + NKP*SB*8)   // 52224

// pack two f32 -> bf16x2 in ONE instruction (lo -> lower half, hi -> upper half)
__device__ __forceinline__ uint32_t packbf2(float lo, float hi) {
    uint32_t r;
    asm("cvt.rn.bf16x2.f32 %0, %1, %2;" : "=r"(r) : "f"(hi), "f"(lo));
    return r;
}

// split a pair (v0 -> lower, v1 -> upper) into packed bf16 hi/lo pairs
__device__ __forceinline__ void split_pair(float v0, float v1, uint32_t& hp, uint32_t& lp) {
    hp = packbf2(v0, v1);
    float h0 = __uint_as_float(hp << 16);          // bf16(v0) as f32
    float h1 = __uint_as_float(hp & 0xFFFF0000u);  // bf16(v1) as f32
    lp = packbf2(v0 - h0, v1 - h1);                // exact residuals
}

__device__ __forceinline__ void mma16(float* d, uint32_t a0, uint32_t a1, uint32_t a2, uint32_t a3,
                                      uint32_t b0, uint32_t b1) {
    asm volatile(
        "mma.sync.aligned.m16n8k16.row.col.f32.bf16.bf16.f32 "
        "{%0,%1,%2,%3}, {%4,%5,%6,%7}, {%8,%9}, {%0,%1,%2,%3};"
        : "+f"(d[0]), "+f"(d[1]), "+f"(d[2]), "+f"(d[3])
        : "r"(a0), "r"(a1), "r"(a2), "r"(a3), "r"(b0), "r"(b1));
}

__global__ __launch_bounds__(THREADS, 2)
void bmm_bf16_kernel(const float* __restrict__ x,
                     const float* __restrict__ attn,
                     const float* __restrict__ Dm,
                     const float* __restrict__ alpha,
                     float* __restrict__ out)
{
    extern __shared__ __align__(16) char sm[];
    uint2* Apk = (uint2*)sm;                       // [64 p][36] (hi-pair, lo-pair)
    uint2* Bpk = (uint2*)(sm + MPAD * SA * 8);     // [32 kpairs][132 c]
    float* Ysh = (float*)Bpk;                      // Y[c*49+p] (25088 B) post-MMA

    const int n   = blockIdx.y;
    const int c0  = blockIdx.x * CT;
    const int tid = threadIdx.x;
    const int wid = tid >> 5;
    const int lid = tid & 31;
    const int g   = lid >> 2;     // groupID
    const int t   = lid & 3;      // thread-in-group

    // ---- stage A = attn[n]: bf16 hi/lo k-pairs, zero-padded 64 x 32kp ----
    const float* An = attn + (size_t)n * HW * HW;
    for (int i = tid; i < MPAD * NKP; i += THREADS) {   // 4 iters
        int p = i >> 5, j = i & 31;                     // kpair j -> q = 2j, 2j+1
        float v0 = 0.f, v1 = 0.f;
        if (p < HW) {
            int q0 = 2 * j;
            if (q0 < HW)     v0 = An[p * HW + q0];
            if (q0 + 1 < HW) v1 = An[p * HW + q0 + 1];
        }
        uint32_t hp, lp;
        split_pair(v0, v1, hp, lp);
        Apk[p * SA + j] = make_uint2(hp, lp);
    }

    // ---- stage B = D[n][q][c0..c0+127]: bf16 hi/lo k-pairs [kpair][c] ----
    const float* Dn = Dm + (size_t)n * HW * CCOLS + c0;
    for (int i = tid; i < NKP * (CT / 4); i += THREADS) {   // 2 iters
        int j = i >> 5, c4 = i & 31;                        // kpair j, c = 4*c4
        int q0 = 2 * j;
        float4 u = (q0 < HW)     ? *(const float4*)(Dn + (size_t)q0 * CCOLS + 4 * c4)
                                 : make_float4(0.f, 0.f, 0.f, 0.f);
        float4 w = (q0 + 1 < HW) ? *(const float4*)(Dn + (size_t)(q0 + 1) * CCOLS + 4 * c4)
                                 : make_float4(0.f, 0.f, 0.f, 0.f);
        const float ue[4] = {u.x, u.y, u.z, u.w};
        const float we[4] = {w.x, w.y, w.z, w.w};
        uint2* dst = Bpk + j * SB + 4 * c4;
#pragma unroll
        for (int e = 0; e < 4; ++e) {                       // (k even -> lo, k odd -> hi)
            uint32_t hp, lp;
            split_pair(ue[e], we[e], hp, lp);
            dst[e] = make_uint2(hp, lp);
        }
    }
    __syncthreads();

    // ---- mainloop: 16 warps = 4 m-tiles x 4 n-quarters; 4 k16 steps ----
    const int mb = (wid & 3) * 16;
    const int nb = (wid >> 2) * 32;

    float acc[4][4];
#pragma unroll
    for (int nt = 0; nt < 4; ++nt)
#pragma unroll
        for (int d = 0; d < 4; ++d) acc[nt][d] = 0.f;

    const uint2* aP = Apk + (mb + g) * SA + t;
    const uint2* bP = Bpk + t * SB + nb + g;

#pragma unroll
    for (int ks = 0; ks < 4; ++ks) {               // kpairs 8ks .. 8ks+7
        uint2 A0 = aP[8 * ks];
        uint2 A1 = aP[8 * SA + 8 * ks];
        uint2 A2 = aP[8 * ks + 4];
        uint2 A3 = aP[8 * SA + 8 * ks + 4];
#pragma unroll
        for (int nt = 0; nt < 4; ++nt) {
            uint2 B0 = bP[(8 * ks) * SB + 8 * nt];
            uint2 B1 = bP[(8 * ks + 4) * SB + 8 * nt];
            mma16(acc[nt], A0.x, A1.x, A2.x, A3.x, B0.x, B1.x);   // Ah*Bh
            mma16(acc[nt], A0.y, A1.y, A2.y, A3.y, B0.x, B1.x);   // Al*Bh
            mma16(acc[nt], A0.x, A1.x, A2.x, A3.x, B0.y, B1.y);   // Ah*Bl
        }
    }
    __syncthreads();     // all B reads done — safe to reuse region as Y

    // ---- scatter Y[c][p] into smem for contiguous gmem writes ----
    {
        const int p0 = mb + g, p1 = p0 + 8;
#pragma unroll
        for (int nt = 0; nt < 4; ++nt) {
            const int c = nb + nt * 8 + 2 * t;
            if (p0 < HW) {
                Ysh[c * HW + p0]       = acc[nt][0];
                Ysh[(c + 1) * HW + p0] = acc[nt][1];
            }
            if (p1 < HW) {
                Ysh[c * HW + p1]       = acc[nt][2];
                Ysh[(c + 1) * HW + p1] = acc[nt][3];
            }
        }
    }
    __syncthreads();

    // ---- residual epilogue: out[n, c0:c0+128, :] contiguous (6272 floats) ----
    const float  al_  = alpha[0];
    const size_t base = (size_t)n * CCOLS * HW + (size_t)c0 * HW;
    const float4* x4  = (const float4*)(x + base);
    const float4* y4  = (const float4*)Ysh;
    float4*       o4  = (float4*)(out + base);
    for (int i = tid; i < (CT * HW) / 4; i += THREADS) {   // 1568
        float4 xv = x4[i], yv = y4[i], ov;
        ov.x = fmaf(al_, yv.x, xv.x);
        ov.y = fmaf(al_, yv.y, xv.y);
        ov.z = fmaf(al_, yv.z, xv.z);
        ov.w = fmaf(al_, yv.w, xv.w);
        o4[i] = ov;
    }
}

extern "C" void kernel_launch(void* const* d_in, const int* in_sizes, int n_in,
                              void* d_out, int out_size)
{
    const float* x     = (const float*)d_in[0];
    const float* attn  = (const float*)d_in[1];
    const float* Dm    = (const float*)d_in[2];
    const float* alpha = (const float*)d_in[3];
    float*       out   = (float*)d_out;

    cudaFuncSetAttribute(bmm_bf16_kernel, cudaFuncAttributeMaxDynamicSharedMemorySize, SMEM_BYTES);

    const int N = in_sizes[1] / (HW * HW);   // 2048
    dim3 grid(CCOLS / CT, N);                // (4, 2048)
    bmm_bf16_kernel<<<grid, THREADS, SMEM_BYTES>>>(x, attn, Dm, alpha, out);
}

// round 13
// speedup vs baseline: 1.1849x; 1.1849x over previous
#include <cuda_runtime.h>
#include <stdint.h>

#define HW      49
#define MPAD    64        // p padded
#define CT      64        // c per CTA
#define CCOLS   512
#define THREADS 256
#define SA      36        // A row stride in uint2 (36 ≡ 4 mod 16 -> conflict-free frags)
#define SB      68        // B row stride in uint2 (68 ≡ 4 mod 16 -> conflict-free frags)
#define NKP     32        // kpairs (K padded 49 -> 64)

// smem: Apk[64][36] uint2 (18432 B) | Bpk[32][68] uint2 (17408 B); Y reuses B
#define SMEM_BYTES (MPAD*SA*8 + NKP*SB*8)   // 35840

// pack two f32 -> bf16x2 in ONE instruction (v0 -> lower half, v1 -> upper half)
__device__ __forceinline__ uint32_t packbf2(float v0, float v1) {
    uint32_t r;
    asm("cvt.rn.bf16x2.f32 %0, %1, %2;" : "=r"(r) : "f"(v1), "f"(v0));
    return r;
}

// split a pair into packed bf16 (hi-pair, lo-pair); lo = bf16(v - float(bf16(v)))
__device__ __forceinline__ void split_pair(float v0, float v1, uint32_t& hp, uint32_t& lp) {
    hp = packbf2(v0, v1);
    float h0 = __uint_as_float(hp << 16);          // bf16(v0) as f32
    float h1 = __uint_as_float(hp & 0xFFFF0000u);  // bf16(v1) as f32
    lp = packbf2(v0 - h0, v1 - h1);                // exact residuals, rounded to bf16
}

__device__ __forceinline__ void mma16(float* d, uint32_t a0, uint32_t a1, uint32_t a2, uint32_t a3,
                                      uint32_t b0, uint32_t b1) {
    asm volatile(
        "mma.sync.aligned.m16n8k16.row.col.f32.bf16.bf16.f32 "
        "{%0,%1,%2,%3}, {%4,%5,%6,%7}, {%8,%9}, {%0,%1,%2,%3};"
        : "+f"(d[0]), "+f"(d[1]), "+f"(d[2]), "+f"(d[3])
        : "r"(a0), "r"(a1), "r"(a2), "r"(a3), "r"(b0), "r"(b1));
}

__global__ __launch_bounds__(THREADS, 5)
void bmm_bf16_kernel(const float* __restrict__ x,
                     const float* __restrict__ attn,
                     const float* __restrict__ Dm,
                     const float* __restrict__ alpha,
                     float* __restrict__ out)
{
    extern __shared__ __align__(16) char sm[];
    uint2* Apk = (uint2*)sm;                       // [64 p][36] (hi-pair, lo-pair)
    uint2* Bpk = (uint2*)(sm + MPAD * SA * 8);     // [32 kpairs][68 c]
    float* Ysh = (float*)Bpk;                      // Y[c*49+p] (12544 B) post-MMA

    const int n   = blockIdx.y;
    const int c0  = blockIdx.x * CT;
    const int tid = threadIdx.x;
    const int wid = tid >> 5;
    const int lid = tid & 31;
    const int g   = lid >> 2;     // groupID
    const int t   = lid & 3;      // thread-in-group

    // ---- stage A = attn[n]: bf16 hi/lo k-pairs, zero-padded 64 x 32kp ----
    const float* An = attn + (size_t)n * HW * HW;
    for (int i = tid; i < MPAD * NKP; i += THREADS) {   // 8 iters
        int p = i >> 5, j = i & 31;                     // kpair j -> q = 2j, 2j+1
        float v0 = 0.f, v1 = 0.f;
        if (p < HW) {
            int q0 = 2 * j;
            if (q0 < HW)     v0 = An[p * HW + q0];
            if (q0 + 1 < HW) v1 = An[p * HW + q0 + 1];
        }
        uint32_t hp, lp;
        split_pair(v0, v1, hp, lp);
        Apk[p * SA + j] = make_uint2(hp, lp);
    }

    // ---- stage B = D[n][q][c0..c0+63]: bf16 hi/lo k-pairs [kpair][c] ----
    const float* Dn = Dm + (size_t)n * HW * CCOLS + c0;
    for (int i = tid; i < NKP * (CT / 4); i += THREADS) {   // 2 iters
        int j = i >> 4, c4 = i & 15;                        // kpair j, c = 4*c4
        int q0 = 2 * j;
        float4 u = (q0 < HW)     ? *(const float4*)(Dn + (size_t)q0 * CCOLS + 4 * c4)
                                 : make_float4(0.f, 0.f, 0.f, 0.f);
        float4 w = (q0 + 1 < HW) ? *(const float4*)(Dn + (size_t)(q0 + 1) * CCOLS + 4 * c4)
                                 : make_float4(0.f, 0.f, 0.f, 0.f);
        const float ue[4] = {u.x, u.y, u.z, u.w};
        const float we[4] = {w.x, w.y, w.z, w.w};
        uint2* dst = Bpk + j * SB + 4 * c4;
#pragma unroll
        for (int e = 0; e < 4; ++e) {                       // (k even, k odd)
            uint32_t hp, lp;
            split_pair(ue[e], we[e], hp, lp);
            dst[e] = make_uint2(hp, lp);
        }
    }
    __syncthreads();

    // ---- mainloop: warp = (m-tile = wid&3, n-half = wid>>2); 4 k16 steps ----
    const int mb = (wid & 3) * 16;
    const int nb = (wid >> 2) * 32;

    float acc[4][4];
#pragma unroll
    for (int nt = 0; nt < 4; ++nt)
#pragma unroll
        for (int d = 0; d < 4; ++d) acc[nt][d] = 0.f;

    const uint2* aP = Apk + (mb + g) * SA + t;
    const uint2* bP = Bpk + t * SB + nb + g;

#pragma unroll
    for (int ks = 0; ks < 4; ++ks) {               // kpairs 8ks .. 8ks+7
        uint2 A0 = aP[8 * ks];
        uint2 A1 = aP[8 * SA + 8 * ks];
        uint2 A2 = aP[8 * ks + 4];
        uint2 A3 = aP[8 * SA + 8 * ks + 4];
#pragma unroll
        for (int nt = 0; nt < 4; ++nt) {
            uint2 B0 = bP[(8 * ks) * SB + 8 * nt];
            uint2 B1 = bP[(8 * ks + 4) * SB + 8 * nt];
            mma16(acc[nt], A0.x, A1.x, A2.x, A3.x, B0.x, B1.x);   // Ah*Bh
            mma16(acc[nt], A0.y, A1.y, A2.y, A3.y, B0.x, B1.x);   // Al*Bh
            mma16(acc[nt], A0.x, A1.x, A2.x, A3.x, B0.y, B1.y);   // Ah*Bl
        }
    }

    // ---- prefetch epilogue x NOW (independent of smem) to hide DRAM latency
    //      behind the scatter barriers ----
    const float  al_  = alpha[0];
    const size_t base = (size_t)n * CCOLS * HW + (size_t)c0 * HW;
    const float4* x4  = (const float4*)(x + base);
    const int i0 = tid, i1 = tid + THREADS, i2 = tid + 2 * THREADS, i3 = tid + 3 * THREADS;
    float4 xp0 = x4[i0];                                  // 784 total float4
    float4 xp1 = x4[i1];
    float4 xp2 = x4[i2];
    float4 xp3 = (i3 < (CT * HW) / 4) ? x4[i3] : make_float4(0.f, 0.f, 0.f, 0.f);

    __syncthreads();     // all B reads done — safe to reuse region as Y

    // ---- scatter Y[c][p] into smem for contiguous gmem writes ----
    {
        const int p0 = mb + g, p1 = p0 + 8;
#pragma unroll
        for (int nt = 0; nt < 4; ++nt) {
            const int c = nb + nt * 8 + 2 * t;
            if (p0 < HW) {
                Ysh[c * HW + p0]       = acc[nt][0];
                Ysh[(c + 1) * HW + p0] = acc[nt][1];
            }
            if (p1 < HW) {
                Ysh[c * HW + p1]       = acc[nt][2];
                Ysh[(c + 1) * HW + p1] = acc[nt][3];
            }
        }
    }
    __syncthreads();

    // ---- residual epilogue: out[n, c0:c0+64, :] contiguous (3136 floats) ----
    const float4* y4 = (const float4*)Ysh;
    float4*       o4 = (float4*)(out + base);
    {
        float4 yv, ov;
        yv = y4[i0];
        ov.x = fmaf(al_, yv.x, xp0.x); ov.y = fmaf(al_, yv.y, xp0.y);
        ov.z = fmaf(al_, yv.z, xp0.z); ov.w = fmaf(al_, yv.w, xp0.w);
        o4[i0] = ov;
        yv = y4[i1];
        ov.x = fmaf(al_, yv.x, xp1.x); ov.y = fmaf(al_, yv.y, xp1.y);
        ov.z = fmaf(al_, yv.z, xp1.z); ov.w = fmaf(al_, yv.w, xp1.w);
        o4[i1] = ov;
        yv = y4[i2];
        ov.x = fmaf(al_, yv.x, xp2.x); ov.y = fmaf(al_, yv.y, xp2.y);
        ov.z = fmaf(al_, yv.z, xp2.z); ov.w = fmaf(al_, yv.w, xp2.w);
        o4[i2] = ov;
        if (i3 < (CT * HW) / 4) {
            yv = y4[i3];
            ov.x = fmaf(al_, yv.x, xp3.x); ov.y = fmaf(al_, yv.y, xp3.y);
            ov.z = fmaf(al_, yv.z, xp3.z); ov.w = fmaf(al_, yv.w, xp3.w);
            o4[i3] = ov;
        }
    }
}

extern "C" void kernel_launch(void* const* d_in, const int* in_sizes, int n_in,
                              void* d_out, int out_size)
{
    const float* x     = (const float*)d_in[0];
    const float* attn  = (const float*)d_in[1];
    const float* Dm    = (const float*)d_in[2];
    const float* alpha = (const float*)d_in[3];
    float*       out   = (float*)d_out;

    cudaFuncSetAttribute(bmm_bf16_kernel, cudaFuncAttributeMaxDynamicSharedMemorySize, SMEM_BYTES);

    const int N = in_sizes[1] / (HW * HW);   // 2048
    dim3 grid(CCOLS / CT, N);                // (8, 2048)
    bmm_bf16_kernel<<<grid, THREADS, SMEM_BYTES>>>(x, attn, Dm, alpha, out);
}